// round 15
// baseline (speedup 1.0000x reference)
#include <cuda_runtime.h>
#include <cuda_fp16.h>
#include <cstdint>
#include <math.h>

#define Bz 8
#define Sq 1024
#define Cc 1280
#define Hh 8
#define DHd 160
#define RK 4
#define Mrows (Bz*Sq)      /* 8192 */
#define QKV_N (3*Cc)       /* 3840 */
#define XW 2560            /* activation [hi|lo] fp16 width */
#define BH (Bz*Hh)         /* 64 */

// ====================== helpers ======================
__device__ __forceinline__ uint32_t smem_u32(const void* p) {
    uint32_t a;
    asm("{ .reg .u64 t; cvta.to.shared.u64 t, %1; cvt.u32.u64 %0, t; }" : "=r"(a) : "l"(p));
    return a;
}
__device__ __forceinline__ void cpa16(uint32_t dst, const void* src) {
    asm volatile("cp.async.cg.shared.global [%0], [%1], 16;" :: "r"(dst), "l"(src) : "memory");
}
#define CP_COMMIT asm volatile("cp.async.commit_group;" ::: "memory")
#define CP_WAIT0  asm volatile("cp.async.wait_group 0;" ::: "memory")
#define CP_WAIT1  asm volatile("cp.async.wait_group 1;" ::: "memory")

__device__ __forceinline__ void ldsm4(uint32_t* r, uint32_t addr) {
    asm volatile("ldmatrix.sync.aligned.m8n8.x4.shared.b16 {%0,%1,%2,%3}, [%4];"
                 : "=r"(r[0]), "=r"(r[1]), "=r"(r[2]), "=r"(r[3]) : "r"(addr));
}
__device__ __forceinline__ void mma16816(float* d, const uint32_t* a, const uint32_t* b) {
    asm volatile(
        "mma.sync.aligned.m16n8k16.row.col.f32.f16.f16.f32 "
        "{%0,%1,%2,%3}, {%4,%5,%6,%7}, {%8,%9}, {%0,%1,%2,%3};"
        : "+f"(d[0]), "+f"(d[1]), "+f"(d[2]), "+f"(d[3])
        : "r"(a[0]), "r"(a[1]), "r"(a[2]), "r"(a[3]), "r"(b[0]), "r"(b[1]));
}
__device__ __forceinline__ void split_h(float v, __half& h, __half& l) {
    h = __float2half_rn(v);
    l = __float2half_rn(v - __half2float(h));
}
__device__ __forceinline__ void pack_split2h(float v0, float v1, uint32_t& uh, uint32_t& ul) {
    __half h0, l0, h1, l1;
    split_h(v0, h0, l0);
    split_h(v1, h1, l1);
    __half2 hh, ll;
    hh.x = h0; hh.y = h1; ll.x = l0; ll.y = l1;
    uh = *(uint32_t*)&hh; ul = *(uint32_t*)&ll;
}
__device__ __forceinline__ uint32_t pack2h(float v0, float v1) {
    __half2 hh;
    hh.x = __float2half_rn(v0); hh.y = __float2half_rn(v1);
    return *(uint32_t*)&hh;
}
// write split pair into activation [hi|lo] layout (hi at base, lo at base+Cc)
__device__ __forceinline__ void wr2(__half* Cs, size_t base, float v0, float v1) {
    uint32_t uh, ul;
    pack_split2h(v0, v1, uh, ul);
    *(uint32_t*)(Cs + base)      = uh;
    *(uint32_t*)(Cs + base + Cc) = ul;
}
__device__ __forceinline__ uint32_t swz24(int c, int r) { return (c & 24) | ((c & 7) ^ (r & 7)); }
__device__ __forceinline__ uint32_t swz16(int c, int r) { return (c & 8) | ((c & 7) ^ (r & 7)); }

// ====================== scratch ======================
__device__ __half g_hp1[(size_t)Mrows * Cc];    // h+pose single fp16 (merge is 1-pass)
__device__ __half g_x2[(size_t)Mrows * XW];
__device__ __half g_at2[(size_t)Mrows * XW];
__device__ __half g_wm2[(size_t)Cc * Cc];       // single fp16, [N][1280]
__device__ __half g_we2[(size_t)QKV_N * Cc];
__device__ __half g_wo2[(size_t)Cc * Cc];
__device__ float g_vf[(size_t)Mrows * Cc];      // V fp32 (for transpose)
__device__ __half g_qc[(size_t)BH * Sq * 320];  // Q [hi160|lo160]
__device__ __half g_kc[(size_t)BH * Sq * 160];  // K single fp16
__device__ __half g_vc[(size_t)BH * DHd * 1024];// V^T single fp16 [d][s]

// ====================== prep kernels ======================
__global__ void k_add_h(const float* __restrict__ a, const float* __restrict__ b,
                        __half* __restrict__ dst) {
    int i = blockIdx.x * 256 + threadIdx.x;       // pair index
    if (i >= Mrows * Cc / 2) return;
    int gi = i * 2;
    *(uint32_t*)(dst + gi) = pack2h(a[gi] + b[gi], a[gi + 1] + b[gi + 1]);
}

// all-5 weight transpose + LoRA fold -> single fp16 [N][1280]
struct WTArgs {
    const float* W[5];
    const float* dn[5];
    const float* up[5];
};
__global__ void k_wT_all(WTArgs args, __half* __restrict__ wm2,
                         __half* __restrict__ we2, __half* __restrict__ wo2) {
    __shared__ float t[32][33];
    const int tid = threadIdx.x;
    const int z = blockIdx.z;
    const int k0 = blockIdx.y * 32, n0 = blockIdx.x * 32;
    const float* W = args.W[z];
    const float* dn = args.dn[z];
    const float* up = args.up[z];
    __half* dst = (z == 0) ? wm2 : (z == 4) ? wo2 : we2;
    const int dstoff = (z >= 1 && z <= 3) ? (z - 1) * Cc : 0;
#pragma unroll
    for (int j = 0; j < 4; j++) {
        int idx = tid + j * 256;
        int kr = idx >> 5, nc = idx & 31;
        float s = W[(size_t)(k0 + kr) * Cc + n0 + nc];
        if (dn != nullptr) {
#pragma unroll
            for (int r = 0; r < RK; r++)
                s += dn[(k0 + kr) * RK + r] * up[r * Cc + n0 + nc];
        }
        t[kr][nc] = s;
    }
    __syncthreads();
#pragma unroll
    for (int j = 0; j < 2; j++) {
        int idx = tid + j * 256;
        int nr = idx >> 4, kc = (idx & 15) * 2;
        *(uint32_t*)(dst + (size_t)(dstoff + n0 + nr) * Cc + k0 + kc) =
            pack2h(t[kc][nr], t[kc + 1][nr]);
    }
}

// build vc: [bh][d(160)][s(1024)] single fp16 (transpose of g_vf)
__global__ void k_vc(const float* __restrict__ vf, __half* __restrict__ vc) {
    __shared__ float t[32][33];
    const int tid = threadIdx.x;
    const int bh = blockIdx.z, b = bh >> 3, h = bh & 7;
    const int s0 = blockIdx.y * 32, d0 = blockIdx.x * 32;
#pragma unroll
    for (int j = 0; j < 4; j++) {
        int idx = tid + j * 256;
        int sr = idx >> 5, dc = idx & 31;
        t[sr][dc] = vf[((size_t)b * Sq + s0 + sr) * Cc + h * DHd + d0 + dc];
    }
    __syncthreads();
#pragma unroll
    for (int j = 0; j < 2; j++) {
        int idx = tid + j * 256;
        int dr = idx >> 4, sc = (idx & 15) * 2;
        size_t base = (size_t)bh * DHd * 1024 + (size_t)(d0 + dr) * 1024 + s0 + sc;
        *(uint32_t*)(vc + base) = pack2h(t[sc][dr], t[sc + 1][dr]);
    }
}

// ====================== dense HMMA GEMM (fp16 split) ======================
// C[M,N] = A @ Bfp16[N,1280]^T in 20 chunks of 64.
// MODE 1 (merge): A single fp16 [M][1280], 1 MMA pass; +bias+resid, wr2 split out.
// MODE 2 (out):   A split [M][2560], 2 passes; +bias, fp32 out.
// MODE 3 (qkv):   A split, 2 passes; epilogue -> qc split, kc single, v fp32.
// 128x128 CTA tile, 8 warps (2M x 4N -> 64x32), 2-slot double buffer, 2 CTAs/SM.
#define SLOT 49152
template <int MODE>
__global__ void __launch_bounds__(256, 2) k_mma(
    const __half* __restrict__ A, const __half* __restrict__ B,
    float* __restrict__ Cf, __half* __restrict__ Cs,
    const float* __restrict__ bias, const float* __restrict__ resid, int N,
    __half* __restrict__ qc, __half* __restrict__ kc,
    float* __restrict__ vf) {
    extern __shared__ char sm[];
    const uint32_t sb = smem_u32(sm);
    const int tid = threadIdx.x, lane = tid & 31, wid = tid >> 5;
    const int m0 = blockIdx.y * 128, n0 = blockIdx.x * 128;
    const int wm = (wid >> 2) * 64, wn = (wid & 3) * 32;
    const int lda = (MODE == 1) ? Cc : XW;

    float acc[4][4][4] = {};

#define LOAD_STAGE(s, c) do { \
        const uint32_t bs_ = sb + (s) * SLOT; \
        const __half* Ap = A + (size_t)m0 * lda + (c) * 64; \
        const __half* Bp = B + (size_t)n0 * Cc + (c) * 64; \
        _Pragma("unroll") \
        for (int i = 0; i < 4; i++) { \
            int pos = tid + i * 256; \
            int row = pos >> 3, ch = pos & 7; \
            int sw = ch ^ (row & 7); \
            cpa16(bs_ + row * 128 + sw * 16, Ap + (size_t)row * lda + ch * 8); \
            if (MODE != 1) \
                cpa16(bs_ + 16384 + row * 128 + sw * 16, Ap + 1280 + (size_t)row * lda + ch * 8); \
            cpa16(bs_ + 32768 + row * 128 + sw * 16, Bp + (size_t)row * Cc + ch * 8); \
        } \
    } while (0)

    LOAD_STAGE(0, 0); CP_COMMIT;

    const int row_in = (lane & 7) + ((lane >> 3) & 1) * 8;
    const int choff = (lane >> 4);

    for (int c = 0; c < 20; c++) {
        CP_WAIT0;
        __syncthreads();
        if (c + 1 < 20) LOAD_STAGE((c + 1) & 1, c + 1);
        CP_COMMIT;

        const uint32_t Ab = sb + (c & 1) * SLOT;
        const uint32_t Lb = Ab + 16384, Bb = Ab + 32768;
#pragma unroll
        for (int q = 0; q < 4; q++) {
            const int chq = q * 2 + choff;
            uint32_t b[2][4];
#pragma unroll
            for (int f2 = 0; f2 < 2; f2++) {
                int r = wn + f2 * 16 + row_in;
                ldsm4(b[f2], Bb + r * 128 + ((chq ^ (r & 7)) * 16));
            }
#pragma unroll
            for (int fm = 0; fm < 4; fm++) {
                int r = wm + fm * 16 + row_in;
                uint32_t off = r * 128 + ((chq ^ (r & 7)) * 16);
                uint32_t ahi[4];
                ldsm4(ahi, Ab + off);
#pragma unroll
                for (int fn = 0; fn < 4; fn++) {
                    uint32_t bb[2] = { b[fn >> 1][fn & 1], b[fn >> 1][(fn & 1) + 2] };
                    mma16816(acc[fm][fn], ahi, bb);
                }
                if (MODE != 1) {
                    uint32_t alo[4];
                    ldsm4(alo, Lb + off);
#pragma unroll
                    for (int fn = 0; fn < 4; fn++) {
                        uint32_t bb[2] = { b[fn >> 1][fn & 1], b[fn >> 1][(fn & 1) + 2] };
                        mma16816(acc[fm][fn], alo, bb);
                    }
                }
            }
        }
    }
#undef LOAD_STAGE

    const int rbase = m0 + wm + (lane >> 2);
    const int cbase = n0 + wn + (lane & 3) * 2;
#pragma unroll
    for (int fm = 0; fm < 4; fm++) {
#pragma unroll
        for (int fn = 0; fn < 4; fn++) {
            const int col = cbase + fn * 8;
#pragma unroll
            for (int half = 0; half < 2; half++) {
                const int row = rbase + fm * 16 + half * 8;
                float v0 = acc[fm][fn][half * 2 + 0];
                float v1 = acc[fm][fn][half * 2 + 1];
                if (MODE == 1 || MODE == 2) {
                    float2 bb = *(const float2*)(bias + col);
                    v0 += bb.x; v1 += bb.y;
                }
                if (MODE == 1) {
                    float2 rr = *(const float2*)(resid + (size_t)row * Cc + col);
                    v0 += rr.x; v1 += rr.y;
                    wr2(Cs, (size_t)row * XW + col, v0, v1);
                } else if (MODE == 3) {
                    const int brow = row >> 10, srow = row & 1023;
                    if (col < Cc) {                 // Q: split
                        const int hh = col / DHd, d = col - hh * DHd;
                        __half* dst = qc + ((size_t)((brow << 3) + hh) * Sq + srow) * 320 + d;
                        uint32_t uh, ul;
                        pack_split2h(v0, v1, uh, ul);
                        *(uint32_t*)dst = uh;
                        *(uint32_t*)(dst + DHd) = ul;
                    } else if (col < 2 * Cc) {      // K: single fp16
                        const int ch = col - Cc;
                        const int hh = ch / DHd, d = ch - hh * DHd;
                        __half* dst = kc + ((size_t)((brow << 3) + hh) * Sq + srow) * 160 + d;
                        *(uint32_t*)dst = pack2h(v0, v1);
                    } else {                        // V: fp32 for transpose
                        float2 ov; ov.x = v0; ov.y = v1;
                        *(float2*)(vf + (size_t)row * Cc + (col - 2 * Cc)) = ov;
                    }
                } else {
                    float2 ov; ov.x = v0; ov.y = v1;
                    *(float2*)(Cf + (size_t)row * N + col) = ov;
                }
            }
        }
    }
}

// ====================== flash attention (fp16 2-pass split) ======================
// smem: QLO[128][384B] | KHI[128][384B] | VHI[160][256B]
#define FL_QLO 0
#define FL_KHI 49152
#define FL_VHI 98304
#define FL_SMEM 139264

__global__ void __launch_bounds__(256, 1) k_flash(
    const __half* __restrict__ qc, const __half* __restrict__ kc,
    const __half* __restrict__ vc, __half* __restrict__ at2) {
    extern __shared__ char sm[];
    const uint32_t sb = smem_u32(sm);
    const int tid = threadIdx.x, lane = tid & 31, wid = tid >> 5;
    const int qt = blockIdx.x, bh = blockIdx.y;
    const int b = bh >> 3, h = bh & 7;
    const char* qB = (const char*)qc + ((size_t)bh * Sq + qt * 128) * 640;
    const char* kB = (const char*)kc + ((size_t)bh * Sq) * 320;
    const char* vB = (const char*)vc + (size_t)bh * DHd * 2048;

    const int row_in = (lane & 7) + ((lane >> 3) & 1) * 8;
    const int choff = lane >> 4;
    const int lrow = tid >> 1, lhalf = tid & 1;

    // prologue: stage Qhi (in KHI area) + Qlo (persistent QLO)
#pragma unroll
    for (int j = 0; j < 10; j++) {
        int c = lhalf * 10 + j;
        cpa16(sb + FL_KHI + lrow * 384 + swz24(c, lrow) * 16, qB + lrow * 640 + c * 16);
        cpa16(sb + FL_QLO + lrow * 384 + swz24(c, lrow) * 16, qB + lrow * 640 + 320 + c * 16);
    }
    CP_COMMIT;
    CP_WAIT0;
    __syncthreads();

    uint32_t qhi[10][4];
    {
        int r = wid * 16 + row_in;
#pragma unroll
        for (int kf = 0; kf < 10; kf++)
            ldsm4(qhi[kf], sb + FL_KHI + r * 384 + swz24(2 * kf + choff, r) * 16);
    }
    __syncthreads();   // KHI staging free before K(0) load

#define LOAD_K(kt) do { \
        const char* kr = kB + ((kt) * 128 + lrow) * 320; \
        _Pragma("unroll") \
        for (int j = 0; j < 10; j++) { \
            int c = lhalf * 10 + j; \
            cpa16(sb + FL_KHI + lrow * 384 + swz24(c, lrow) * 16, kr + c * 16); \
        } \
    } while (0)
#define LOAD_V(kt) do { \
        _Pragma("unroll") \
        for (int i = 0; i < 10; i++) { \
            int idx = tid + i * 256; \
            int vr = idx >> 4, c = idx & 15; \
            cpa16(sb + FL_VHI + vr * 256 + swz16(c, vr) * 16, \
                  vB + vr * 2048 + (kt) * 256 + c * 16); \
        } \
    } while (0)

    LOAD_K(0); CP_COMMIT;
    LOAD_V(0); CP_COMMIT;

    float O[20][4] = {};
    float mr0 = -1e30f, mr1 = -1e30f, lr0 = 0.f, lr1 = 0.f;
    const float cs = 0.07905694150420949f * 1.4426950408889634f;
    const int rq = wid * 16 + row_in;

    for (int kt = 0; kt < 8; kt++) {
        CP_WAIT1;
        __syncthreads();

        float accS[16][4] = {};
#pragma unroll
        for (int kf = 0; kf < 10; kf++) {
            uint32_t qlo[4];
            ldsm4(qlo, sb + FL_QLO + rq * 384 + swz24(2 * kf + choff, rq) * 16);
#pragma unroll
            for (int g = 0; g < 8; g++) {
                int r = g * 16 + row_in;
                uint32_t bhi[4];
                ldsm4(bhi, sb + FL_KHI + r * 384 + swz24(2 * kf + choff, r) * 16);
                uint32_t b0[2] = { bhi[0], bhi[2] }, b1[2] = { bhi[1], bhi[3] };
                mma16816(accS[2 * g],     qhi[kf], b0);
                mma16816(accS[2 * g + 1], qhi[kf], b1);
                mma16816(accS[2 * g],     qlo,     b0);
                mma16816(accS[2 * g + 1], qlo,     b1);
            }
        }

        float mx0 = -1e30f, mx1 = -1e30f;
#pragma unroll
        for (int nf = 0; nf < 16; nf++) {
            mx0 = fmaxf(mx0, fmaxf(accS[nf][0], accS[nf][1]));
            mx1 = fmaxf(mx1, fmaxf(accS[nf][2], accS[nf][3]));
        }
        mx0 = fmaxf(mx0, __shfl_xor_sync(0xffffffffu, mx0, 1));
        mx0 = fmaxf(mx0, __shfl_xor_sync(0xffffffffu, mx0, 2));
        mx1 = fmaxf(mx1, __shfl_xor_sync(0xffffffffu, mx1, 1));
        mx1 = fmaxf(mx1, __shfl_xor_sync(0xffffffffu, mx1, 2));
        float mn0 = fmaxf(mr0, mx0), mn1 = fmaxf(mr1, mx1);
        float a0 = exp2f((mr0 - mn0) * cs), a1 = exp2f((mr1 - mn1) * cs);
        float s0 = 0.f, s1 = 0.f;
#pragma unroll
        for (int nf = 0; nf < 16; nf++) {
            accS[nf][0] = exp2f((accS[nf][0] - mn0) * cs);
            accS[nf][1] = exp2f((accS[nf][1] - mn0) * cs);
            accS[nf][2] = exp2f((accS[nf][2] - mn1) * cs);
            accS[nf][3] = exp2f((accS[nf][3] - mn1) * cs);
            s0 += accS[nf][0] + accS[nf][1];
            s1 += accS[nf][2] + accS[nf][3];
        }
        s0 += __shfl_xor_sync(0xffffffffu, s0, 1);
        s0 += __shfl_xor_sync(0xffffffffu, s0, 2);
        s1 += __shfl_xor_sync(0xffffffffu, s1, 1);
        s1 += __shfl_xor_sync(0xffffffffu, s1, 2);
        lr0 = lr0 * a0 + s0;
        lr1 = lr1 * a1 + s1;
        mr0 = mn0; mr1 = mn1;
#pragma unroll
        for (int nf = 0; nf < 20; nf++) {
            O[nf][0] *= a0; O[nf][1] *= a0; O[nf][2] *= a1; O[nf][3] *= a1;
        }

        __syncthreads();
        if (kt < 7) { LOAD_K(kt + 1); }
        CP_COMMIT;
        CP_WAIT1;
        __syncthreads();

#pragma unroll
        for (int kf = 0; kf < 8; kf++) {
            uint32_t phi[4], plo[4];
            pack_split2h(accS[2 * kf][0],     accS[2 * kf][1],     phi[0], plo[0]);
            pack_split2h(accS[2 * kf][2],     accS[2 * kf][3],     phi[1], plo[1]);
            pack_split2h(accS[2 * kf + 1][0], accS[2 * kf + 1][1], phi[2], plo[2]);
            pack_split2h(accS[2 * kf + 1][2], accS[2 * kf + 1][3], phi[3], plo[3]);
#pragma unroll
            for (int g = 0; g < 10; g++) {
                int r = g * 16 + row_in;
                uint32_t bhi[4];
                ldsm4(bhi, sb + FL_VHI + r * 256 + swz16(2 * kf + choff, r) * 16);
                uint32_t b0[2] = { bhi[0], bhi[2] }, b1[2] = { bhi[1], bhi[3] };
                mma16816(O[2 * g],     phi, b0);
                mma16816(O[2 * g + 1], phi, b1);
                mma16816(O[2 * g],     plo, b0);
                mma16816(O[2 * g + 1], plo, b1);
            }
        }

        __syncthreads();
        if (kt < 7) { LOAD_V(kt + 1); }
        CP_COMMIT;
    }

    // epilogue: O/l -> compact split at2
    float i0 = 1.0f / lr0, i1 = 1.0f / lr1;
    int r0 = qt * 128 + wid * 16 + (lane >> 2);
#pragma unroll
    for (int nf = 0; nf < 20; nf++) {
        int d = nf * 8 + (lane & 3) * 2;
        size_t base0 = ((size_t)(b * Sq + r0) * XW) + h * DHd + d;
        size_t base1 = ((size_t)(b * Sq + r0 + 8) * XW) + h * DHd + d;
        wr2(at2, base0, O[nf][0] * i0, O[nf][1] * i0);
        wr2(at2, base1, O[nf][2] * i1, O[nf][3] * i1);
    }
#undef LOAD_K
#undef LOAD_V
}

// ====================== launch ======================
#define GEMM_SMEM (2 * SLOT)

extern "C" void kernel_launch(void* const* d_in, const int* in_sizes, int n_in,
                              void* d_out, int out_size) {
    const float* h  = (const float*)d_in[0];
    const float* p  = (const float*)d_in[1];
    const float* Wm = (const float*)d_in[2];
    const float* bm = (const float*)d_in[3];
    const float* wq = (const float*)d_in[4];
    const float* wk = (const float*)d_in[5];
    const float* wv = (const float*)d_in[6];
    const float* wo = (const float*)d_in[7];
    const float* bo = (const float*)d_in[8];
    const float* qd = (const float*)d_in[9];
    const float* qu = (const float*)d_in[10];
    const float* kd = (const float*)d_in[11];
    const float* ku = (const float*)d_in[12];
    const float* vd = (const float*)d_in[13];
    const float* vu = (const float*)d_in[14];
    const float* od = (const float*)d_in[15];
    const float* ou = (const float*)d_in[16];

    __half *hp1, *x2, *at2, *wm2, *we2, *wo2, *qc, *kc, *vc;
    float *vf;
    cudaGetSymbolAddress((void**)&hp1, g_hp1);
    cudaGetSymbolAddress((void**)&x2, g_x2);
    cudaGetSymbolAddress((void**)&at2, g_at2);
    cudaGetSymbolAddress((void**)&wm2, g_wm2);
    cudaGetSymbolAddress((void**)&we2, g_we2);
    cudaGetSymbolAddress((void**)&wo2, g_wo2);
    cudaGetSymbolAddress((void**)&vf, g_vf);
    cudaGetSymbolAddress((void**)&qc, g_qc);
    cudaGetSymbolAddress((void**)&kc, g_kc);
    cudaGetSymbolAddress((void**)&vc, g_vc);

    cudaFuncSetAttribute(k_mma<1>, cudaFuncAttributeMaxDynamicSharedMemorySize, GEMM_SMEM);
    cudaFuncSetAttribute(k_mma<2>, cudaFuncAttributeMaxDynamicSharedMemorySize, GEMM_SMEM);
    cudaFuncSetAttribute(k_mma<3>, cudaFuncAttributeMaxDynamicSharedMemorySize, GEMM_SMEM);
    cudaFuncSetAttribute(k_flash, cudaFuncAttributeMaxDynamicSharedMemorySize, FL_SMEM);

    // 1) hp = h + pose (single fp16; merge GEMM is 1-pass)
    k_add_h<<<(Mrows * Cc / 2 + 255) / 256, 256>>>(h, p, hp1);

    // 2) weight prep (all 5 in one launch)
    {
        WTArgs wa;
        wa.W[0] = Wm; wa.dn[0] = nullptr; wa.up[0] = nullptr;
        wa.W[1] = wq; wa.dn[1] = qd; wa.up[1] = qu;
        wa.W[2] = wk; wa.dn[2] = kd; wa.up[2] = ku;
        wa.W[3] = wv; wa.dn[3] = vd; wa.up[3] = vu;
        wa.W[4] = wo; wa.dn[4] = od; wa.up[4] = ou;
        k_wT_all<<<dim3(Cc / 32, Cc / 32, 5), 256>>>(wa, wm2, we2, wo2);
    }

    // 3) x = hp @ Wm + bm + h  -> split x'  (merge term tiny -> 1-pass exact enough)
    k_mma<1><<<dim3(Cc / 128, Mrows / 128), 256, GEMM_SMEM>>>(
        hp1, wm2, nullptr, x2, bm, h, Cc, nullptr, nullptr, nullptr);

    // 4) qkv = x @ [Wq|Wk|Wv] -> qc split + kc single + v fp32
    k_mma<3><<<dim3(QKV_N / 128, Mrows / 128), 256, GEMM_SMEM>>>(
        x2, we2, nullptr, nullptr, nullptr, nullptr, QKV_N, qc, kc, vf);

    // 5) V transpose (single fp16)
    k_vc<<<dim3(DHd / 32, Sq / 32, BH), 256>>>(vf, vc);

    // 6) fused flash attention -> split at2
    k_flash<<<dim3(Sq / 128, BH), 256, FL_SMEM>>>(qc, kc, vc, at2);

    // 7) out = attn @ Wo + bo (fp32 to d_out)
    k_mma<2><<<dim3(Cc / 128, Mrows / 128), 256, GEMM_SMEM>>>(
        at2, wo2, (float*)d_out, nullptr, bo, nullptr, Cc, nullptr, nullptr, nullptr);
}

// round 16
// speedup vs baseline: 1.5350x; 1.5350x over previous
#include <cuda_runtime.h>
#include <cuda_fp16.h>
#include <cstdint>
#include <math.h>

#define Bz 8
#define Sq 1024
#define Cc 1280
#define Hh 8
#define DHd 160
#define RK 4
#define Mrows (Bz*Sq)      /* 8192 */
#define QKV_N (3*Cc)       /* 3840 */
#define XW 2560            /* activation [hi|lo] fp16 width */
#define BH (Bz*Hh)         /* 64 */

// ====================== helpers ======================
__device__ __forceinline__ uint32_t smem_u32(const void* p) {
    uint32_t a;
    asm("{ .reg .u64 t; cvta.to.shared.u64 t, %1; cvt.u32.u64 %0, t; }" : "=r"(a) : "l"(p));
    return a;
}
__device__ __forceinline__ void cpa16(uint32_t dst, const void* src) {
    asm volatile("cp.async.cg.shared.global [%0], [%1], 16;" :: "r"(dst), "l"(src) : "memory");
}
#define CP_COMMIT asm volatile("cp.async.commit_group;" ::: "memory")
#define CP_WAIT0  asm volatile("cp.async.wait_group 0;" ::: "memory")
#define CP_WAIT1  asm volatile("cp.async.wait_group 1;" ::: "memory")

__device__ __forceinline__ void ldsm4(uint32_t* r, uint32_t addr) {
    asm volatile("ldmatrix.sync.aligned.m8n8.x4.shared.b16 {%0,%1,%2,%3}, [%4];"
                 : "=r"(r[0]), "=r"(r[1]), "=r"(r[2]), "=r"(r[3]) : "r"(addr));
}
__device__ __forceinline__ void mma16816(float* d, const uint32_t* a, const uint32_t* b) {
    asm volatile(
        "mma.sync.aligned.m16n8k16.row.col.f32.f16.f16.f32 "
        "{%0,%1,%2,%3}, {%4,%5,%6,%7}, {%8,%9}, {%0,%1,%2,%3};"
        : "+f"(d[0]), "+f"(d[1]), "+f"(d[2]), "+f"(d[3])
        : "r"(a[0]), "r"(a[1]), "r"(a[2]), "r"(a[3]), "r"(b[0]), "r"(b[1]));
}
__device__ __forceinline__ void split_h(float v, __half& h, __half& l) {
    h = __float2half_rn(v);
    l = __float2half_rn(v - __half2float(h));
}
__device__ __forceinline__ void pack_split2h(float v0, float v1, uint32_t& uh, uint32_t& ul) {
    __half h0, l0, h1, l1;
    split_h(v0, h0, l0);
    split_h(v1, h1, l1);
    __half2 hh, ll;
    hh.x = h0; hh.y = h1; ll.x = l0; ll.y = l1;
    uh = *(uint32_t*)&hh; ul = *(uint32_t*)&ll;
}
__device__ __forceinline__ uint32_t pack2h(float v0, float v1) {
    __half2 hh;
    hh.x = __float2half_rn(v0); hh.y = __float2half_rn(v1);
    return *(uint32_t*)&hh;
}
// write split pair into activation [hi|lo] layout (hi at base, lo at base+Cc)
__device__ __forceinline__ void wr2(__half* Cs, size_t base, float v0, float v1) {
    uint32_t uh, ul;
    pack_split2h(v0, v1, uh, ul);
    *(uint32_t*)(Cs + base)      = uh;
    *(uint32_t*)(Cs + base + Cc) = ul;
}
__device__ __forceinline__ uint32_t swz24(int c, int r) { return (c & 24) | ((c & 7) ^ (r & 7)); }
__device__ __forceinline__ uint32_t swz16(int c, int r) { return (c & 8) | ((c & 7) ^ (r & 7)); }

// ====================== scratch ======================
__device__ __half g_hp1[(size_t)Mrows * Cc];    // h+pose single fp16 (merge is 1-pass)
__device__ __half g_x2[(size_t)Mrows * XW];
__device__ __half g_at2[(size_t)Mrows * XW];
__device__ __half g_wm2[(size_t)Cc * Cc];       // single fp16, [N][1280]
__device__ __half g_we2[(size_t)QKV_N * Cc];
__device__ __half g_wo2[(size_t)Cc * Cc];
__device__ float g_vf[(size_t)Mrows * Cc];      // V fp32 (for transpose)
__device__ __half g_qc[(size_t)BH * Sq * 320];  // Q [hi160|lo160]
__device__ __half g_kc[(size_t)BH * Sq * 160];  // K single fp16
__device__ __half g_vc[(size_t)BH * DHd * 1024];// V^T single fp16 [d][s]

// ====================== prep kernels ======================
__global__ void k_add_h(const float* __restrict__ a, const float* __restrict__ b,
                        __half* __restrict__ dst) {
    int i = blockIdx.x * 256 + threadIdx.x;       // pair index
    if (i >= Mrows * Cc / 2) return;
    int gi = i * 2;
    *(uint32_t*)(dst + gi) = pack2h(a[gi] + b[gi], a[gi + 1] + b[gi + 1]);
}

// all-5 weight transpose + LoRA fold -> single fp16 [N][1280]
struct WTArgs {
    const float* W[5];
    const float* dn[5];
    const float* up[5];
};
__global__ void k_wT_all(WTArgs args, __half* __restrict__ wm2,
                         __half* __restrict__ we2, __half* __restrict__ wo2) {
    __shared__ float t[32][33];
    const int tid = threadIdx.x;
    const int z = blockIdx.z;
    const int k0 = blockIdx.y * 32, n0 = blockIdx.x * 32;
    const float* W = args.W[z];
    const float* dn = args.dn[z];
    const float* up = args.up[z];
    __half* dst = (z == 0) ? wm2 : (z == 4) ? wo2 : we2;
    const int dstoff = (z >= 1 && z <= 3) ? (z - 1) * Cc : 0;
#pragma unroll
    for (int j = 0; j < 4; j++) {
        int idx = tid + j * 256;
        int kr = idx >> 5, nc = idx & 31;
        float s = W[(size_t)(k0 + kr) * Cc + n0 + nc];
        if (dn != nullptr) {
#pragma unroll
            for (int r = 0; r < RK; r++)
                s += dn[(k0 + kr) * RK + r] * up[r * Cc + n0 + nc];
        }
        t[kr][nc] = s;
    }
    __syncthreads();
#pragma unroll
    for (int j = 0; j < 2; j++) {
        int idx = tid + j * 256;
        int nr = idx >> 4, kc = (idx & 15) * 2;
        *(uint32_t*)(dst + (size_t)(dstoff + n0 + nr) * Cc + k0 + kc) =
            pack2h(t[kc][nr], t[kc + 1][nr]);
    }
}

// build vc: [bh][d(160)][s(1024)] single fp16 (transpose of g_vf)
__global__ void k_vc(const float* __restrict__ vf, __half* __restrict__ vc) {
    __shared__ float t[32][33];
    const int tid = threadIdx.x;
    const int bh = blockIdx.z, b = bh >> 3, h = bh & 7;
    const int s0 = blockIdx.y * 32, d0 = blockIdx.x * 32;
#pragma unroll
    for (int j = 0; j < 4; j++) {
        int idx = tid + j * 256;
        int sr = idx >> 5, dc = idx & 31;
        t[sr][dc] = vf[((size_t)b * Sq + s0 + sr) * Cc + h * DHd + d0 + dc];
    }
    __syncthreads();
#pragma unroll
    for (int j = 0; j < 2; j++) {
        int idx = tid + j * 256;
        int dr = idx >> 4, sc = (idx & 15) * 2;
        size_t base = (size_t)bh * DHd * 1024 + (size_t)(d0 + dr) * 1024 + s0 + sc;
        *(uint32_t*)(vc + base) = pack2h(t[sc][dr], t[sc + 1][dr]);
    }
}

// ====================== dense HMMA GEMM (fp16 split) ======================
// C[M,N] = A @ Bfp16[N,1280]^T in 20 chunks of 64.
// MODE 1 (merge): A single fp16 [M][1280], 1 MMA pass; +bias+resid, wr2 split out.
// MODE 2 (out):   A split [M][2560], 2 passes; +bias, fp32 out.
// MODE 3 (qkv):   A split, 2 passes; epilogue -> qc split, kc single, v fp32.
// 128x128 CTA tile, 8 warps (2M x 4N -> 64x32), 2-slot double buffer, 2 CTAs/SM.
#define SLOT 49152
template <int MODE>
__global__ void __launch_bounds__(256, 2) k_mma(
    const __half* __restrict__ A, const __half* __restrict__ B,
    float* __restrict__ Cf, __half* __restrict__ Cs,
    const float* __restrict__ bias, const float* __restrict__ resid, int N,
    __half* __restrict__ qc, __half* __restrict__ kc,
    float* __restrict__ vf) {
    extern __shared__ char sm[];
    const uint32_t sb = smem_u32(sm);
    const int tid = threadIdx.x, lane = tid & 31, wid = tid >> 5;
    const int m0 = blockIdx.y * 128, n0 = blockIdx.x * 128;
    const int wm = (wid >> 2) * 64, wn = (wid & 3) * 32;
    const int lda = (MODE == 1) ? Cc : XW;

    float acc[4][4][4] = {};

#define LOAD_STAGE(s, c) do { \
        const uint32_t bs_ = sb + (s) * SLOT; \
        const __half* Ap = A + (size_t)m0 * lda + (c) * 64; \
        const __half* Bp = B + (size_t)n0 * Cc + (c) * 64; \
        _Pragma("unroll") \
        for (int i = 0; i < 4; i++) { \
            int pos = tid + i * 256; \
            int row = pos >> 3, ch = pos & 7; \
            int sw = ch ^ (row & 7); \
            cpa16(bs_ + row * 128 + sw * 16, Ap + (size_t)row * lda + ch * 8); \
            if (MODE != 1) \
                cpa16(bs_ + 16384 + row * 128 + sw * 16, Ap + 1280 + (size_t)row * lda + ch * 8); \
            cpa16(bs_ + 32768 + row * 128 + sw * 16, Bp + (size_t)row * Cc + ch * 8); \
        } \
    } while (0)

    LOAD_STAGE(0, 0); CP_COMMIT;

    const int row_in = (lane & 7) + ((lane >> 3) & 1) * 8;
    const int choff = (lane >> 4);

    for (int c = 0; c < 20; c++) {
        CP_WAIT0;
        __syncthreads();
        if (c + 1 < 20) LOAD_STAGE((c + 1) & 1, c + 1);
        CP_COMMIT;

        const uint32_t Ab = sb + (c & 1) * SLOT;
        const uint32_t Lb = Ab + 16384, Bb = Ab + 32768;
#pragma unroll
        for (int q = 0; q < 4; q++) {
            const int chq = q * 2 + choff;
            uint32_t b[2][4];
#pragma unroll
            for (int f2 = 0; f2 < 2; f2++) {
                int r = wn + f2 * 16 + row_in;
                ldsm4(b[f2], Bb + r * 128 + ((chq ^ (r & 7)) * 16));
            }
#pragma unroll
            for (int fm = 0; fm < 4; fm++) {
                int r = wm + fm * 16 + row_in;
                uint32_t off = r * 128 + ((chq ^ (r & 7)) * 16);
                uint32_t ahi[4];
                ldsm4(ahi, Ab + off);
#pragma unroll
                for (int fn = 0; fn < 4; fn++) {
                    uint32_t bb[2] = { b[fn >> 1][fn & 1], b[fn >> 1][(fn & 1) + 2] };
                    mma16816(acc[fm][fn], ahi, bb);
                }
                if (MODE != 1) {
                    uint32_t alo[4];
                    ldsm4(alo, Lb + off);
#pragma unroll
                    for (int fn = 0; fn < 4; fn++) {
                        uint32_t bb[2] = { b[fn >> 1][fn & 1], b[fn >> 1][(fn & 1) + 2] };
                        mma16816(acc[fm][fn], alo, bb);
                    }
                }
            }
        }
    }
#undef LOAD_STAGE

    const int rbase = m0 + wm + (lane >> 2);
    const int cbase = n0 + wn + (lane & 3) * 2;
#pragma unroll
    for (int fm = 0; fm < 4; fm++) {
#pragma unroll
        for (int fn = 0; fn < 4; fn++) {
            const int col = cbase + fn * 8;
#pragma unroll
            for (int half = 0; half < 2; half++) {
                const int row = rbase + fm * 16 + half * 8;
                float v0 = acc[fm][fn][half * 2 + 0];
                float v1 = acc[fm][fn][half * 2 + 1];
                if (MODE == 1 || MODE == 2) {
                    float2 bb = *(const float2*)(bias + col);
                    v0 += bb.x; v1 += bb.y;
                }
                if (MODE == 1) {
                    float2 rr = *(const float2*)(resid + (size_t)row * Cc + col);
                    v0 += rr.x; v1 += rr.y;
                    wr2(Cs, (size_t)row * XW + col, v0, v1);
                } else if (MODE == 3) {
                    const int brow = row >> 10, srow = row & 1023;
                    if (col < Cc) {                 // Q: split
                        const int hh = col / DHd, d = col - hh * DHd;
                        __half* dst = qc + ((size_t)((brow << 3) + hh) * Sq + srow) * 320 + d;
                        uint32_t uh, ul;
                        pack_split2h(v0, v1, uh, ul);
                        *(uint32_t*)dst = uh;
                        *(uint32_t*)(dst + DHd) = ul;
                    } else if (col < 2 * Cc) {      // K: single fp16
                        const int ch = col - Cc;
                        const int hh = ch / DHd, d = ch - hh * DHd;
                        __half* dst = kc + ((size_t)((brow << 3) + hh) * Sq + srow) * 160 + d;
                        *(uint32_t*)dst = pack2h(v0, v1);
                    } else {                        // V: fp32 for transpose
                        float2 ov; ov.x = v0; ov.y = v1;
                        *(float2*)(vf + (size_t)row * Cc + (col - 2 * Cc)) = ov;
                    }
                } else {
                    float2 ov; ov.x = v0; ov.y = v1;
                    *(float2*)(Cf + (size_t)row * N + col) = ov;
                }
            }
        }
    }
}

// ====================== flash attention (fp16 2-pass split) ======================
// smem: QLO[128][384B] | KHI[128][384B] | VHI[160][256B]
#define FL_QLO 0
#define FL_KHI 49152
#define FL_VHI 98304
#define FL_SMEM 139264

__global__ void __launch_bounds__(256, 1) k_flash(
    const __half* __restrict__ qc, const __half* __restrict__ kc,
    const __half* __restrict__ vc, __half* __restrict__ at2) {
    extern __shared__ char sm[];
    const uint32_t sb = smem_u32(sm);
    const int tid = threadIdx.x, lane = tid & 31, wid = tid >> 5;
    const int qt = blockIdx.x, bh = blockIdx.y;
    const int b = bh >> 3, h = bh & 7;
    const char* qB = (const char*)qc + ((size_t)bh * Sq + qt * 128) * 640;
    const char* kB = (const char*)kc + ((size_t)bh * Sq) * 320;
    const char* vB = (const char*)vc + (size_t)bh * DHd * 2048;

    const int row_in = (lane & 7) + ((lane >> 3) & 1) * 8;
    const int choff = lane >> 4;
    const int lrow = tid >> 1, lhalf = tid & 1;

    // prologue: stage Qhi (in KHI area) + Qlo (persistent QLO)
#pragma unroll
    for (int j = 0; j < 10; j++) {
        int c = lhalf * 10 + j;
        cpa16(sb + FL_KHI + lrow * 384 + swz24(c, lrow) * 16, qB + lrow * 640 + c * 16);
        cpa16(sb + FL_QLO + lrow * 384 + swz24(c, lrow) * 16, qB + lrow * 640 + 320 + c * 16);
    }
    CP_COMMIT;
    CP_WAIT0;
    __syncthreads();

    uint32_t qhi[10][4];
    {
        int r = wid * 16 + row_in;
#pragma unroll
        for (int kf = 0; kf < 10; kf++)
            ldsm4(qhi[kf], sb + FL_KHI + r * 384 + swz24(2 * kf + choff, r) * 16);
    }
    __syncthreads();   // KHI staging free before K(0) load

#define LOAD_K(kt) do { \
        const char* kr = kB + ((kt) * 128 + lrow) * 320; \
        _Pragma("unroll") \
        for (int j = 0; j < 10; j++) { \
            int c = lhalf * 10 + j; \
            cpa16(sb + FL_KHI + lrow * 384 + swz24(c, lrow) * 16, kr + c * 16); \
        } \
    } while (0)
#define LOAD_V(kt) do { \
        _Pragma("unroll") \
        for (int i = 0; i < 10; i++) { \
            int idx = tid + i * 256; \
            int vr = idx >> 4, c = idx & 15; \
            cpa16(sb + FL_VHI + vr * 256 + swz16(c, vr) * 16, \
                  vB + vr * 2048 + (kt) * 256 + c * 16); \
        } \
    } while (0)

    LOAD_K(0); CP_COMMIT;
    LOAD_V(0); CP_COMMIT;

    float O[20][4] = {};
    float mr0 = -1e30f, mr1 = -1e30f, lr0 = 0.f, lr1 = 0.f;
    const float cs = 0.07905694150420949f * 1.4426950408889634f;
    const int rq = wid * 16 + row_in;

    for (int kt = 0; kt < 8; kt++) {
        CP_WAIT1;
        __syncthreads();

        float accS[16][4] = {};
#pragma unroll
        for (int kf = 0; kf < 10; kf++) {
            uint32_t qlo[4];
            ldsm4(qlo, sb + FL_QLO + rq * 384 + swz24(2 * kf + choff, rq) * 16);
#pragma unroll
            for (int g = 0; g < 8; g++) {
                int r = g * 16 + row_in;
                uint32_t bhi[4];
                ldsm4(bhi, sb + FL_KHI + r * 384 + swz24(2 * kf + choff, r) * 16);
                uint32_t b0[2] = { bhi[0], bhi[2] }, b1[2] = { bhi[1], bhi[3] };
                mma16816(accS[2 * g],     qhi[kf], b0);
                mma16816(accS[2 * g + 1], qhi[kf], b1);
                mma16816(accS[2 * g],     qlo,     b0);
                mma16816(accS[2 * g + 1], qlo,     b1);
            }
        }

        float mx0 = -1e30f, mx1 = -1e30f;
#pragma unroll
        for (int nf = 0; nf < 16; nf++) {
            mx0 = fmaxf(mx0, fmaxf(accS[nf][0], accS[nf][1]));
            mx1 = fmaxf(mx1, fmaxf(accS[nf][2], accS[nf][3]));
        }
        mx0 = fmaxf(mx0, __shfl_xor_sync(0xffffffffu, mx0, 1));
        mx0 = fmaxf(mx0, __shfl_xor_sync(0xffffffffu, mx0, 2));
        mx1 = fmaxf(mx1, __shfl_xor_sync(0xffffffffu, mx1, 1));
        mx1 = fmaxf(mx1, __shfl_xor_sync(0xffffffffu, mx1, 2));
        float mn0 = fmaxf(mr0, mx0), mn1 = fmaxf(mr1, mx1);
        float a0 = exp2f((mr0 - mn0) * cs), a1 = exp2f((mr1 - mn1) * cs);
        float s0 = 0.f, s1 = 0.f;
#pragma unroll
        for (int nf = 0; nf < 16; nf++) {
            accS[nf][0] = exp2f((accS[nf][0] - mn0) * cs);
            accS[nf][1] = exp2f((accS[nf][1] - mn0) * cs);
            accS[nf][2] = exp2f((accS[nf][2] - mn1) * cs);
            accS[nf][3] = exp2f((accS[nf][3] - mn1) * cs);
            s0 += accS[nf][0] + accS[nf][1];
            s1 += accS[nf][2] + accS[nf][3];
        }
        s0 += __shfl_xor_sync(0xffffffffu, s0, 1);
        s0 += __shfl_xor_sync(0xffffffffu, s0, 2);
        s1 += __shfl_xor_sync(0xffffffffu, s1, 1);
        s1 += __shfl_xor_sync(0xffffffffu, s1, 2);
        lr0 = lr0 * a0 + s0;
        lr1 = lr1 * a1 + s1;
        mr0 = mn0; mr1 = mn1;
#pragma unroll
        for (int nf = 0; nf < 20; nf++) {
            O[nf][0] *= a0; O[nf][1] *= a0; O[nf][2] *= a1; O[nf][3] *= a1;
        }

        __syncthreads();
        if (kt < 7) { LOAD_K(kt + 1); }
        CP_COMMIT;
        CP_WAIT1;
        __syncthreads();

#pragma unroll
        for (int kf = 0; kf < 8; kf++) {
            uint32_t phi[4], plo[4];
            pack_split2h(accS[2 * kf][0],     accS[2 * kf][1],     phi[0], plo[0]);
            pack_split2h(accS[2 * kf][2],     accS[2 * kf][3],     phi[1], plo[1]);
            pack_split2h(accS[2 * kf + 1][0], accS[2 * kf + 1][1], phi[2], plo[2]);
            pack_split2h(accS[2 * kf + 1][2], accS[2 * kf + 1][3], phi[3], plo[3]);
#pragma unroll
            for (int g = 0; g < 10; g++) {
                int r = g * 16 + row_in;
                uint32_t bhi[4];
                ldsm4(bhi, sb + FL_VHI + r * 256 + swz16(2 * kf + choff, r) * 16);
                uint32_t b0[2] = { bhi[0], bhi[2] }, b1[2] = { bhi[1], bhi[3] };
                mma16816(O[2 * g],     phi, b0);
                mma16816(O[2 * g + 1], phi, b1);
                mma16816(O[2 * g],     plo, b0);
                mma16816(O[2 * g + 1], plo, b1);
            }
        }

        __syncthreads();
        if (kt < 7) { LOAD_V(kt + 1); }
        CP_COMMIT;
    }

    // epilogue: O/l -> compact split at2
    float i0 = 1.0f / lr0, i1 = 1.0f / lr1;
    int r0 = qt * 128 + wid * 16 + (lane >> 2);
#pragma unroll
    for (int nf = 0; nf < 20; nf++) {
        int d = nf * 8 + (lane & 3) * 2;
        size_t base0 = ((size_t)(b * Sq + r0) * XW) + h * DHd + d;
        size_t base1 = ((size_t)(b * Sq + r0 + 8) * XW) + h * DHd + d;
        wr2(at2, base0, O[nf][0] * i0, O[nf][1] * i0);
        wr2(at2, base1, O[nf][2] * i1, O[nf][3] * i1);
    }
#undef LOAD_K
#undef LOAD_V
}

// ====================== launch ======================
#define GEMM_SMEM (2 * SLOT)

extern "C" void kernel_launch(void* const* d_in, const int* in_sizes, int n_in,
                              void* d_out, int out_size) {
    const float* h  = (const float*)d_in[0];
    const float* p  = (const float*)d_in[1];
    const float* Wm = (const float*)d_in[2];
    const float* bm = (const float*)d_in[3];
    const float* wq = (const float*)d_in[4];
    const float* wk = (const float*)d_in[5];
    const float* wv = (const float*)d_in[6];
    const float* wo = (const float*)d_in[7];
    const float* bo = (const float*)d_in[8];
    const float* qd = (const float*)d_in[9];
    const float* qu = (const float*)d_in[10];
    const float* kd = (const float*)d_in[11];
    const float* ku = (const float*)d_in[12];
    const float* vd = (const float*)d_in[13];
    const float* vu = (const float*)d_in[14];
    const float* od = (const float*)d_in[15];
    const float* ou = (const float*)d_in[16];

    __half *hp1, *x2, *at2, *wm2, *we2, *wo2, *qc, *kc, *vc;
    float *vf;
    cudaGetSymbolAddress((void**)&hp1, g_hp1);
    cudaGetSymbolAddress((void**)&x2, g_x2);
    cudaGetSymbolAddress((void**)&at2, g_at2);
    cudaGetSymbolAddress((void**)&wm2, g_wm2);
    cudaGetSymbolAddress((void**)&we2, g_we2);
    cudaGetSymbolAddress((void**)&wo2, g_wo2);
    cudaGetSymbolAddress((void**)&vf, g_vf);
    cudaGetSymbolAddress((void**)&qc, g_qc);
    cudaGetSymbolAddress((void**)&kc, g_kc);
    cudaGetSymbolAddress((void**)&vc, g_vc);

    cudaFuncSetAttribute(k_mma<1>, cudaFuncAttributeMaxDynamicSharedMemorySize, GEMM_SMEM);
    cudaFuncSetAttribute(k_mma<2>, cudaFuncAttributeMaxDynamicSharedMemorySize, GEMM_SMEM);
    cudaFuncSetAttribute(k_mma<3>, cudaFuncAttributeMaxDynamicSharedMemorySize, GEMM_SMEM);
    cudaFuncSetAttribute(k_flash, cudaFuncAttributeMaxDynamicSharedMemorySize, FL_SMEM);

    // 1) hp = h + pose (single fp16; merge GEMM is 1-pass)
    k_add_h<<<(Mrows * Cc / 2 + 255) / 256, 256>>>(h, p, hp1);

    // 2) weight prep (all 5 in one launch)
    {
        WTArgs wa;
        wa.W[0] = Wm; wa.dn[0] = nullptr; wa.up[0] = nullptr;
        wa.W[1] = wq; wa.dn[1] = qd; wa.up[1] = qu;
        wa.W[2] = wk; wa.dn[2] = kd; wa.up[2] = ku;
        wa.W[3] = wv; wa.dn[3] = vd; wa.up[3] = vu;
        wa.W[4] = wo; wa.dn[4] = od; wa.up[4] = ou;
        k_wT_all<<<dim3(Cc / 32, Cc / 32, 5), 256>>>(wa, wm2, we2, wo2);
    }

    // 3) x = hp @ Wm + bm + h  -> split x'  (merge term tiny -> 1-pass exact enough)
    k_mma<1><<<dim3(Cc / 128, Mrows / 128), 256, GEMM_SMEM>>>(
        hp1, wm2, nullptr, x2, bm, h, Cc, nullptr, nullptr, nullptr);

    // 4) qkv = x @ [Wq|Wk|Wv] -> qc split + kc single + v fp32
    k_mma<3><<<dim3(QKV_N / 128, Mrows / 128), 256, GEMM_SMEM>>>(
        x2, we2, nullptr, nullptr, nullptr, nullptr, QKV_N, qc, kc, vf);

    // 5) V transpose (single fp16)
    k_vc<<<dim3(DHd / 32, Sq / 32, BH), 256>>>(vf, vc);

    // 6) fused flash attention -> split at2
    k_flash<<<dim3(Sq / 128, BH), 256, FL_SMEM>>>(qc, kc, vc, at2);

    // 7) out = attn @ Wo + bo (fp32 to d_out)
    k_mma<2><<<dim3(Cc / 128, Mrows / 128), 256, GEMM_SMEM>>>(
        at2, wo2, (float*)d_out, nullptr, bo, nullptr, Cc, nullptr, nullptr, nullptr);
}